// round 1
// baseline (speedup 1.0000x reference)
#include <cuda_runtime.h>
#include <math.h>

// Problem dims (fixed by the reference)
#define BB   2
#define SEQ  2048
#define DIM  768
#define NH   12
#define DHD  64
#define FFD  3072
#define PDIM 64
#define NROW (BB*SEQ)      // 4096

// ---------------- scratch (device globals; no cudaMalloc allowed) ----------
__device__ __align__(16) float g_xn[NROW*DIM];                    // 12.6 MB
__device__ __align__(16) float g_qk[NROW*2*DIM];                  // 25.2 MB (q | k)
__device__ __align__(16) float g_phase[NROW*PDIM];                // 1 MB
__device__ __align__(16) float g_scores[(size_t)BB*NH*SEQ*SEQ];   // 402 MB (raw -> exp)
__device__              float g_invl[BB*NH*SEQ];
__device__ __align__(16) float g_pc[(size_t)BB*SEQ*SEQ];          // 33.5 MB
__device__ __align__(16) float g_blend[(size_t)BB*SEQ*SEQ];       // 33.5 MB
__device__              float g_rowsum[BB*SEQ];
__device__ __align__(16) float g_xmid[NROW*DIM];
__device__ __align__(16) float g_x2[NROW*DIM];
__device__ __align__(16) float g_hbuf[NROW*FFD];                  // 50 MB

// ---------------- helpers ---------------------------------------------------
__device__ __forceinline__ float warpReduceSum(float v) {
#pragma unroll
    for (int o = 16; o > 0; o >>= 1) v += __shfl_xor_sync(0xffffffffu, v, o);
    return v;
}
__device__ __forceinline__ float warpReduceMax(float v) {
#pragma unroll
    for (int o = 16; o > 0; o >>= 1) v = fmaxf(v, __shfl_xor_sync(0xffffffffu, v, o));
    return v;
}
// blockDim.x == 256 assumed
__device__ __forceinline__ float blockReduceSum256(float v, float* sm) {
    v = warpReduceSum(v);
    if ((threadIdx.x & 31) == 0) sm[threadIdx.x >> 5] = v;
    __syncthreads();
    float r;
    if (threadIdx.x < 32) {
        float t = (threadIdx.x < 8) ? sm[threadIdx.x] : 0.0f;
        t = warpReduceSum(t);
        if (threadIdx.x == 0) sm[0] = t;
    }
    __syncthreads();
    r = sm[0];
    __syncthreads();
    return r;
}
__device__ __forceinline__ float blockReduceMax256(float v, float* sm) {
    v = warpReduceMax(v);
    if ((threadIdx.x & 31) == 0) sm[threadIdx.x >> 5] = v;
    __syncthreads();
    float r;
    if (threadIdx.x < 32) {
        float t = (threadIdx.x < 8) ? sm[threadIdx.x] : -3.4e38f;
        t = warpReduceMax(t);
        if (threadIdx.x == 0) sm[0] = t;
    }
    __syncthreads();
    r = sm[0];
    __syncthreads();
    return r;
}

// Fast exp on the FMA/ALU pipes (no MUFU): exp(x) = 2^(x*log2e),
// magic-number round-to-int + degree-5 poly for 2^f, f in [-0.5, 0.5].
// Max rel err ~3e-6 — far inside the 1e-3 budget.
__device__ __forceinline__ float fast_exp(float x) {
    x = fmaxf(x, -87.0f);
    float y  = x * 1.4426950408889634f;
    float z  = y + 12582912.0f;                 // 1.5 * 2^23
    float nf = z - 12582912.0f;
    float f  = y - nf;
    float p  = 1.3333558146e-3f;
    p = fmaf(p, f, 9.6181291076e-3f);
    p = fmaf(p, f, 5.5504108665e-2f);
    p = fmaf(p, f, 2.4022650696e-1f);
    p = fmaf(p, f, 6.9314718056e-1f);
    p = fmaf(p, f, 1.0f);
    unsigned sb = ((unsigned)__float_as_int(z) + (unsigned)(127 - 0x4B400000)) << 23;
    return p * __int_as_float(sb);
}

// ---------------- LayerNorm (one block per row, 256 thr, D=768) ------------
__global__ void __launch_bounds__(256) ln_kernel(
    const float* __restrict__ x, const float* __restrict__ w,
    const float* __restrict__ b, float* __restrict__ o)
{
    __shared__ float sm[8];
    const float* xr = x + (size_t)blockIdx.x * DIM;
    int t = threadIdx.x;
    float v0 = xr[t], v1 = xr[t + 256], v2 = xr[t + 512];
    float mean = blockReduceSum256(v0 + v1 + v2, sm) * (1.0f / DIM);
    float d0 = v0 - mean, d1 = v1 - mean, d2 = v2 - mean;
    float var = blockReduceSum256(d0*d0 + d1*d1 + d2*d2, sm) * (1.0f / DIM);
    float r = rsqrtf(var + 1e-5f);
    float* orow = o + (size_t)blockIdx.x * DIM;
    orow[t      ] = d0 * r * w[t      ] + b[t      ];
    orow[t + 256] = d1 * r * w[t + 256] + b[t + 256];
    orow[t + 512] = d2 * r * w[t + 512] + b[t + 512];
}

// ---------------- generic tiled SGEMM: C = epi(A @ op(B)) -------------------
// A row-major [M,K] (lda). TRB=true: B row-major [N,K] (ldb) -> C=A@B^T.
// TRB=false: B row-major [K,N] (ldb) -> C=A@B.
// Batched via blockIdx.z with composite index z=(z1*zdiv+z2) strides.
// EPI: 0=scale, 1=+bias, 2=tanh, 3=bias+exact GELU, 4=bias+residual,
//      5=row-divide(rowsum)+residual
template<bool TRB, int EPI>
__global__ void __launch_bounds__(256) sgemm(
    const float* __restrict__ A, const float* __restrict__ Bm,
    float* __restrict__ C,
    int M, int N, int K, int lda, int ldb, int ldc,
    int zdiv,
    long as1, long as2, long bs1, long bs2, long cs1, long cs2,
    float scale,
    const float* __restrict__ bias,
    const float* __restrict__ res, long ress1,
    const float* __restrict__ rsum, long rsums1)
{
    const int BM = 128, BN = 64, BK = 16, TM = 8, TN = 4;
    int z = blockIdx.z;
    int z1 = z / zdiv, z2 = z - z1 * zdiv;
    A  += z1 * as1 + z2 * as2;
    Bm += z1 * bs1 + z2 * bs2;
    C  += z1 * cs1 + z2 * cs2;
    if (EPI == 4 || EPI == 5) res  += z1 * ress1;
    if (EPI == 5)             rsum += z1 * rsums1;

    __shared__ float As[BK][BM + 4];
    __shared__ float Bs[BK][BN + 4];

    int tid = threadIdx.x;
    int tx = tid & 15, ty = tid >> 4;
    int bm = blockIdx.x * BM, bn = blockIdx.y * BN;

    float acc[TM][TN];
#pragma unroll
    for (int i = 0; i < TM; i++)
#pragma unroll
        for (int j = 0; j < TN; j++) acc[i][j] = 0.0f;

    const float* Ab = A + (size_t)bm * lda;

    for (int k0 = 0; k0 < K; k0 += BK) {
        // A tile: 128x16 = 512 float4, 2 per thread, stored transposed
#pragma unroll
        for (int i = 0; i < 2; i++) {
            int id = tid + i * 256;
            int r = id >> 2;
            int c = (id & 3) << 2;
            const float4 v = *(const float4*)(Ab + (size_t)r * lda + (k0 + c));
            As[c + 0][r] = v.x; As[c + 1][r] = v.y;
            As[c + 2][r] = v.z; As[c + 3][r] = v.w;
        }
        if (TRB) {
            int r = tid >> 2;
            int c = (tid & 3) << 2;
            const float4 v = *(const float4*)(Bm + (size_t)(bn + r) * ldb + (k0 + c));
            Bs[c + 0][r] = v.x; Bs[c + 1][r] = v.y;
            Bs[c + 2][r] = v.z; Bs[c + 3][r] = v.w;
        } else {
            int r = tid >> 4;
            int c = (tid & 15) << 2;
            const float4 v = *(const float4*)(Bm + (size_t)(k0 + r) * ldb + (bn + c));
            *(float4*)&Bs[r][c] = v;
        }
        __syncthreads();
#pragma unroll
        for (int kk = 0; kk < BK; kk++) {
            float af[TM], bf[TN];
            *(float4*)&af[0] = *(const float4*)&As[kk][ty * TM];
            *(float4*)&af[4] = *(const float4*)&As[kk][ty * TM + 4];
            *(float4*)&bf[0] = *(const float4*)&Bs[kk][tx * TN];
#pragma unroll
            for (int i = 0; i < TM; i++)
#pragma unroll
                for (int j = 0; j < TN; j++)
                    acc[i][j] = fmaf(af[i], bf[j], acc[i][j]);
        }
        __syncthreads();
    }

#pragma unroll
    for (int i = 0; i < TM; i++) {
        int m  = bm + ty * TM + i;
        int n0 = bn + tx * TN;
        float rinv = 0.0f;
        if (EPI == 5) rinv = 1.0f / rsum[m];
        float vv[TN];
#pragma unroll
        for (int j = 0; j < TN; j++) {
            float v = acc[i][j];
            int n = n0 + j;
            if (EPI == 0) v *= scale;
            if (EPI == 1) v += bias[n];
            if (EPI == 2) v = tanhf(v);
            if (EPI == 3) { v += bias[n]; v = 0.5f * v * (1.0f + erff(v * 0.70710678118654752f)); }
            if (EPI == 4) { v = v + bias[n] + res[(size_t)m * ldc + n]; }
            if (EPI == 5) { v = v * rinv + res[(size_t)m * ldc + n]; }
            vv[j] = v;
        }
        float4 o; o.x = vv[0]; o.y = vv[1]; o.z = vv[2]; o.w = vv[3];
        *(float4*)(C + (size_t)m * ldc + n0) = o;
    }
}

// --------- per-row softmax stats: scores -> exp(s - max), store 1/sum ------
// one block per (b,h,i) row; row held in registers (8 x 256 = 2048)
__global__ void __launch_bounds__(256) softmax_exp_kernel(
    float* __restrict__ sc, float* __restrict__ invl)
{
    __shared__ float sm[8];
    float* row = sc + (size_t)blockIdx.x * SEQ;
    int t = threadIdx.x;
    float v[8];
    float m = -3.4e38f;
#pragma unroll
    for (int i = 0; i < 8; i++) { v[i] = row[t + i * 256]; m = fmaxf(m, v[i]); }
    m = blockReduceMax256(m, sm);
    float s = 0.0f;
#pragma unroll
    for (int i = 0; i < 8; i++) {
        float e = fast_exp(v[i] - m);
        s += e;
        row[t + i * 256] = e;
    }
    s = blockReduceSum256(s, sm);
    if (t == 0) invl[blockIdx.x] = 1.0f / s;
}

// --------- blend: u = (mean_h softmax_h + 1e-6) * exp(alpha*(pc+1)/2) ------
// one block per (b,i) row; also produces the row sum for later normalization
__global__ void __launch_bounds__(256) blend_kernel(
    const float* __restrict__ scoresE, const float* __restrict__ invl,
    const float* __restrict__ pc, float* __restrict__ blend,
    float* __restrict__ rowsum, const float* __restrict__ alphap)
{
    __shared__ float sm[8];
    __shared__ float sinvl[NH];
    int b = blockIdx.x / SEQ;
    int i = blockIdx.x - b * SEQ;
    float alpha = *alphap;
    if (threadIdx.x < NH)
        sinvl[threadIdx.x] = invl[(b * NH + threadIdx.x) * SEQ + i] * (1.0f / NH);
    __syncthreads();

    const float* ebase = scoresE + ((size_t)(b * NH) * SEQ + (size_t)i) * SEQ;
    const float* pcrow = pc + ((size_t)b * SEQ + i) * SEQ;
    float*       brow  = blend + ((size_t)b * SEQ + i) * SEQ;

    float lsum = 0.0f;
    for (int j = threadIdx.x; j < SEQ; j += 256) {
        float w = 1e-6f;
#pragma unroll
        for (int h = 0; h < NH; h++)
            w = fmaf(ebase[(size_t)h * SEQ * SEQ + j], sinvl[h], w);
        float p = (pcrow[j] + 1.0f) * 0.5f;
        float u = w * fast_exp(alpha * p);
        brow[j] = u;
        lsum += u;
    }
    lsum = blockReduceSum256(lsum, sm);
    if (threadIdx.x == 0) rowsum[blockIdx.x] = lsum;
}

// ---------------------------------------------------------------------------
extern "C" void kernel_launch(void* const* d_in, const int* in_sizes, int n_in,
                              void* d_out, int out_size)
{
    const float* x        = (const float*)d_in[0];
    const float* ln1_w    = (const float*)d_in[1];
    const float* ln1_b    = (const float*)d_in[2];
    const float* in_w     = (const float*)d_in[3];   // [3D, D]
    const float* in_b     = (const float*)d_in[4];   // [3D]
    const float* phase_w  = (const float*)d_in[5];   // [PD, D]
    const float* alpha    = (const float*)d_in[6];   // scalar
    const float* ff_w1    = (const float*)d_in[7];   // [F, D]
    const float* ff_b1    = (const float*)d_in[8];
    const float* ff_w2    = (const float*)d_in[9];   // [D, F]
    const float* ff_b2    = (const float*)d_in[10];
    const float* ln2_w    = (const float*)d_in[11];
    const float* ln2_b    = (const float*)d_in[12];
    float* out            = (float*)d_out;

    float *xn, *qk, *phase, *scores, *invl, *pcv, *blend, *rowsum, *xmid, *x2, *hbuf;
    cudaGetSymbolAddress((void**)&xn,     g_xn);
    cudaGetSymbolAddress((void**)&qk,     g_qk);
    cudaGetSymbolAddress((void**)&phase,  g_phase);
    cudaGetSymbolAddress((void**)&scores, g_scores);
    cudaGetSymbolAddress((void**)&invl,   g_invl);
    cudaGetSymbolAddress((void**)&pcv,    g_pc);
    cudaGetSymbolAddress((void**)&blend,  g_blend);
    cudaGetSymbolAddress((void**)&rowsum, g_rowsum);
    cudaGetSymbolAddress((void**)&xmid,   g_xmid);
    cudaGetSymbolAddress((void**)&x2,     g_x2);
    cudaGetSymbolAddress((void**)&hbuf,   g_hbuf);

    // 1) xn = LN1(x)
    ln_kernel<<<NROW, 256>>>(x, ln1_w, ln1_b, xn);

    // 2) qk = xn @ W[0:1536]^T + b[0:1536]     [4096, 1536]
    sgemm<true, 1><<<dim3(NROW/128, 1536/64, 1), 256>>>(
        xn, in_w, qk, NROW, 2*DIM, DIM, DIM, DIM, 2*DIM,
        1, 0,0, 0,0, 0,0, 1.0f, in_b, nullptr, 0, nullptr, 0);

    // 3) phase = tanh(xn @ phase_w^T)          [4096, 64]
    sgemm<true, 2><<<dim3(NROW/128, 1, 1), 256>>>(
        xn, phase_w, phase, NROW, PDIM, DIM, DIM, DIM, PDIM,
        1, 0,0, 0,0, 0,0, 1.0f, nullptr, nullptr, 0, nullptr, 0);

    // 4) scores[b,h] = 0.125 * q_h @ k_h^T     24 x [2048, 2048], K=64
    sgemm<true, 0><<<dim3(SEQ/128, SEQ/64, BB*NH), 256>>>(
        qk, qk + DIM, scores, SEQ, SEQ, DHD, 2*DIM, 2*DIM, SEQ,
        NH, (long)SEQ*2*DIM, (long)DHD,  (long)SEQ*2*DIM, (long)DHD,
            (long)NH*SEQ*SEQ, (long)SEQ*SEQ,
        0.125f, nullptr, nullptr, 0, nullptr, 0);

    // 5) pc[b] = phase @ phase^T               2 x [2048, 2048], K=64
    sgemm<true, 0><<<dim3(SEQ/128, SEQ/64, BB), 256>>>(
        phase, phase, pcv, SEQ, SEQ, PDIM, PDIM, PDIM, SEQ,
        1, (long)SEQ*PDIM, 0, (long)SEQ*PDIM, 0, (long)SEQ*SEQ, 0,
        1.0f, nullptr, nullptr, 0, nullptr, 0);

    // 6) per-head softmax stats: scores <- exp(s - m), invl = 1/sum
    softmax_exp_kernel<<<BB*NH*SEQ, 256>>>(scores, invl);

    // 7) blend weights + row sums
    blend_kernel<<<BB*SEQ, 256>>>(scores, invl, pcv, blend, rowsum, alpha);

    // 8) xmid = x + (blend/rowsum) @ xn        2 x [2048, 768], K=2048
    sgemm<false, 5><<<dim3(SEQ/128, DIM/64, BB), 256>>>(
        blend, xn, xmid, SEQ, DIM, SEQ, SEQ, DIM, DIM,
        1, (long)SEQ*SEQ, 0, (long)SEQ*DIM, 0, (long)SEQ*DIM, 0,
        1.0f, nullptr, x, (long)SEQ*DIM, rowsum, (long)SEQ);

    // 9) x2 = LN2(xmid)
    ln_kernel<<<NROW, 256>>>(xmid, ln2_w, ln2_b, x2);

    // 10) h = gelu(x2 @ ff_w1^T + b1)          [4096, 3072]
    sgemm<true, 3><<<dim3(NROW/128, FFD/64, 1), 256>>>(
        x2, ff_w1, hbuf, NROW, FFD, DIM, DIM, DIM, FFD,
        1, 0,0, 0,0, 0,0, 1.0f, ff_b1, nullptr, 0, nullptr, 0);

    // 11) out = xmid + h @ ff_w2^T + b2        [4096, 768]
    sgemm<true, 4><<<dim3(NROW/128, DIM/64, 1), 256>>>(
        hbuf, ff_w2, out, NROW, DIM, FFD, FFD, FFD, DIM,
        1, 0,0, 0,0, 0,0, 1.0f, ff_b2, xmid, 0, nullptr, 0);

    (void)in_sizes; (void)n_in; (void)out_size;
}